// round 8
// baseline (speedup 1.0000x reference)
#include <cuda_runtime.h>
#include <cuda_fp16.h>
#include <math.h>
#include <stdint.h>

#define TT 4096
#define DD 2048
#define FF 5632
#define EE 8

// ---------------------------------------------------------------------------
// Static scratch (allocation-free per harness rules)
// ---------------------------------------------------------------------------
__device__ int   d_cnt[EE];
__device__ int   d_tok[EE][TT];
__device__ float d_wt[EE][TT];
__device__ __half d_xh[(size_t)TT * DD];
__device__ __half d_xl[(size_t)TT * DD];
__device__ __half d_w1h[(size_t)EE * FF * DD];  // [e][f][d] (B^T)
__device__ __half d_w2h[(size_t)EE * DD * FF];  // [e][d][f] (B^T)
__device__ __half d_Hh[(size_t)EE * TT * FF];   // [e][pos][f]

// ---------------------------------------------------------------------------
// PTX helpers — base-ISA only (no sm_103a-gated features)
// ---------------------------------------------------------------------------
__device__ __forceinline__ uint32_t smem_u32(const void* p) {
    uint32_t a;
    asm("{ .reg .u64 t; cvta.to.shared.u64 t, %1; cvt.u32.u64 %0, t; }"
        : "=r"(a) : "l"(p));
    return a;
}
#define SWZ(o) ((o) ^ (((o) >> 3) & 0x70))

#define CP16(dst, src) \
    asm volatile("cp.async.cg.shared.global [%0], [%1], 16;" \
                 :: "r"(dst), "l"(src))
#define CP16Z(dst, src, sz) \
    asm volatile("cp.async.cg.shared.global [%0], [%1], 16, %2;" \
                 :: "r"(dst), "l"(src), "r"(sz))
#define CP_COMMIT() asm volatile("cp.async.commit_group;" ::: "memory")
#define CP_WAIT0()  asm volatile("cp.async.wait_group 0;" ::: "memory")
#define CP_WAIT1()  asm volatile("cp.async.wait_group 1;" ::: "memory")

__device__ __forceinline__ void ldsm4(uint32_t* r, uint32_t a) {
    asm volatile("ldmatrix.sync.aligned.m8n8.x4.shared.b16 {%0,%1,%2,%3}, [%4];"
                 : "=r"(r[0]), "=r"(r[1]), "=r"(r[2]), "=r"(r[3]) : "r"(a));
}
__device__ __forceinline__ void mma_f16(float* c, const uint32_t* a,
                                        const uint32_t* b) {
    asm volatile(
        "mma.sync.aligned.m16n8k16.row.col.f32.f16.f16.f32 "
        "{%0,%1,%2,%3}, {%4,%5,%6,%7}, {%8,%9}, {%0,%1,%2,%3};"
        : "+f"(c[0]), "+f"(c[1]), "+f"(c[2]), "+f"(c[3])
        : "r"(a[0]), "r"(a[1]), "r"(a[2]), "r"(a[3]), "r"(b[0]), "r"(b[1]));
}
__device__ __forceinline__ float gelu_exact(float h) {
    return 0.5f * h * (1.0f + erff(h * 0.70710678118654752440f));
}

// smem layouts
#define OFF_SROW 0
#define OFF_SWT  512
#define OFF_BIAS 1024
#define OFF_TILE 2048
// GEMM1: 3 tensors/buffer (Ah, Al, B)
#define T1OFF(b, t) (OFF_TILE + ((b) * 3 + (t)) * 16384)
#define SMEM1_BYTES (OFF_TILE + 6 * 16384)
// GEMM2: 2 tensors/buffer (A, B)
#define T2OFF(b, t) (OFF_TILE + ((b) * 2 + (t)) * 16384)
#define SMEM2_BYTES (OFF_TILE + 4 * 16384)

// ---------------------------------------------------------------------------
__global__ void init_kernel(float4* __restrict__ out) {
    size_t i = (size_t)blockIdx.x * blockDim.x + threadIdx.x;
    out[i] = make_float4(0.f, 0.f, 0.f, 0.f);
    if (blockIdx.x == 0 && threadIdx.x < EE) d_cnt[threadIdx.x] = 0;
}

// ---------------------------------------------------------------------------
__global__ void gate_kernel(const float* __restrict__ x,
                            const float* __restrict__ gw,
                            const float* __restrict__ gb) {
    int t = (int)((blockIdx.x * blockDim.x + threadIdx.x) >> 5);
    int lane = threadIdx.x & 31;
    if (t >= TT) return;
    const float* xr = x + (size_t)t * DD;

    float acc[EE];
#pragma unroll
    for (int e = 0; e < EE; e++) acc[e] = 0.f;
    for (int d = lane; d < DD; d += 32) {
        float xv = __ldg(xr + d);
        const float* g = gw + (size_t)d * EE;
#pragma unroll
        for (int e = 0; e < EE; e++) acc[e] = fmaf(xv, __ldg(g + e), acc[e]);
    }
#pragma unroll
    for (int e = 0; e < EE; e++) {
#pragma unroll
        for (int o = 16; o > 0; o >>= 1)
            acc[e] += __shfl_xor_sync(0xffffffffu, acc[e], o);
    }
    if (lane == 0) {
#pragma unroll
        for (int e = 0; e < EE; e++) acc[e] += gb[e];
        float mx = acc[0];
#pragma unroll
        for (int e = 1; e < EE; e++) mx = fmaxf(mx, acc[e]);
        float p[EE]; float s = 0.f;
#pragma unroll
        for (int e = 0; e < EE; e++) { p[e] = expf(acc[e] - mx); s += p[e]; }
        float inv = 1.f / s;
        int i1 = 0; float v1 = p[0];
#pragma unroll
        for (int e = 1; e < EE; e++) if (p[e] > v1) { v1 = p[e]; i1 = e; }
        int i2 = -1; float v2 = -1.f;
#pragma unroll
        for (int e = 0; e < EE; e++)
            if (e != i1 && p[e] > v2) { v2 = p[e]; i2 = e; }
        int pos = atomicAdd(&d_cnt[i1], 1);
        d_tok[i1][pos] = t; d_wt[i1][pos] = v1 * inv;
        pos = atomicAdd(&d_cnt[i2], 1);
        d_tok[i2][pos] = t; d_wt[i2][pos] = v2 * inv;
    }
}

// ---------------------------------------------------------------------------
// x -> (hi, lo) fp16 split
// ---------------------------------------------------------------------------
__global__ void convert_x_kernel(const float4* __restrict__ x4) {
    size_t i = (size_t)blockIdx.x * blockDim.x + threadIdx.x;
    float4 v = x4[i];
    __half h0 = __float2half(v.x), h1 = __float2half(v.y);
    __half h2 = __float2half(v.z), h3 = __float2half(v.w);
    __half l0 = __float2half(v.x - __half2float(h0));
    __half l1 = __float2half(v.y - __half2float(h1));
    __half l2 = __float2half(v.z - __half2float(h2));
    __half l3 = __float2half(v.w - __half2float(h3));
    *(__half2*)(d_xh + i * 4 + 0) = __halves2half2(h0, h1);
    *(__half2*)(d_xh + i * 4 + 2) = __halves2half2(h2, h3);
    *(__half2*)(d_xl + i * 4 + 0) = __halves2half2(l0, l1);
    *(__half2*)(d_xl + i * 4 + 2) = __halves2half2(l2, l3);
}

// ---------------------------------------------------------------------------
// weight transpose to fp16:  src [e][R][C] -> dst [e][C][R]
// ---------------------------------------------------------------------------
__global__ void transpose_kernel(const float* __restrict__ src, int which,
                                 int R, int C) {
    __shared__ float t[32][33];
    int e = blockIdx.z;
    const float* S = src + (size_t)e * R * C;
    __half* DH = (which ? d_w2h : d_w1h) + (size_t)e * R * C;
    int c0 = blockIdx.x * 32, r0 = blockIdx.y * 32;
    int tx = threadIdx.x, ty = threadIdx.y;
#pragma unroll
    for (int j = 0; j < 32; j += 8)
        t[ty + j][tx] = S[(size_t)(r0 + ty + j) * C + c0 + tx];
    __syncthreads();
#pragma unroll
    for (int j = 0; j < 32; j += 8) {
        float v = t[tx][ty + j];
        DH[(size_t)(c0 + ty + j) * R + r0 + tx] = __float2half(v);
    }
}

// ---------------------------------------------------------------------------
// GEMM1 chunk: c += (Ah + Al)(128x64) * B(128x64)^T  (B tiles in [n][k])
// ---------------------------------------------------------------------------
__device__ __forceinline__ void mma_chunk_g1(float c[4][4][4], uint32_t sAh,
                                             uint32_t sAl, uint32_t sBh,
                                             int wm0, int wn0, int lid) {
    int mat = lid >> 3, lr = lid & 7;
#pragma unroll
    for (int ks = 0; ks < 4; ks++) {
        uint32_t ah[4][4], al[4][4], bh[4][2];
#pragma unroll
        for (int i = 0; i < 4; i++) {
            int row = wm0 + i * 16 + ((mat & 1) << 3) + lr;
            int col = ks * 16 + ((mat >> 1) << 3);
            uint32_t off = SWZ((row << 7) + (col << 1));
            ldsm4(ah[i], sAh + off);
            ldsm4(al[i], sAl + off);
        }
#pragma unroll
        for (int jp = 0; jp < 2; jp++) {
            int row = wn0 + jp * 16 + ((mat >> 1) << 3) + lr;
            int col = ks * 16 + ((mat & 1) << 3);
            uint32_t off = SWZ((row << 7) + (col << 1));
            uint32_t t4[4];
            ldsm4(t4, sBh + off);
            bh[jp * 2][0] = t4[0]; bh[jp * 2][1] = t4[1];
            bh[jp * 2 + 1][0] = t4[2]; bh[jp * 2 + 1][1] = t4[3];
        }
#pragma unroll
        for (int i = 0; i < 4; i++)
#pragma unroll
            for (int j = 0; j < 4; j++) {
                mma_f16(c[i][j], ah[i], bh[j]);
                mma_f16(c[i][j], al[i], bh[j]);
            }
    }
}

// ---------------------------------------------------------------------------
// GEMM2 chunk: c += A(128x64) * B(128x64)^T  (single pass)
// ---------------------------------------------------------------------------
__device__ __forceinline__ void mma_chunk_g2(float c[4][4][4], uint32_t sA,
                                             uint32_t sBh, int wm0, int wn0,
                                             int lid) {
    int mat = lid >> 3, lr = lid & 7;
#pragma unroll
    for (int ks = 0; ks < 4; ks++) {
        uint32_t ah[4][4], bh[4][2];
#pragma unroll
        for (int i = 0; i < 4; i++) {
            int row = wm0 + i * 16 + ((mat & 1) << 3) + lr;
            int col = ks * 16 + ((mat >> 1) << 3);
            uint32_t off = SWZ((row << 7) + (col << 1));
            ldsm4(ah[i], sA + off);
        }
#pragma unroll
        for (int jp = 0; jp < 2; jp++) {
            int row = wn0 + jp * 16 + ((mat >> 1) << 3) + lr;
            int col = ks * 16 + ((mat & 1) << 3);
            uint32_t off = SWZ((row << 7) + (col << 1));
            uint32_t t4[4];
            ldsm4(t4, sBh + off);
            bh[jp * 2][0] = t4[0]; bh[jp * 2][1] = t4[1];
            bh[jp * 2 + 1][0] = t4[2]; bh[jp * 2 + 1][1] = t4[3];
        }
#pragma unroll
        for (int i = 0; i < 4; i++)
#pragma unroll
            for (int j = 0; j < 4; j++) mma_f16(c[i][j], ah[i], bh[j]);
    }
}

// ---------------------------------------------------------------------------
// GEMM1: H[e,m,:] = gelu( x[tok] @ W1[e] + b1[e] ) -> fp16
// ---------------------------------------------------------------------------
__global__ __launch_bounds__(256, 2) void moe_mma1_kernel(
    const float* __restrict__ b1) {
    extern __shared__ char sm[];
    int e = blockIdx.z;
    int ne = d_cnt[e];
    int m0 = blockIdx.y * 128;
    if (m0 >= ne) return;
    int n0 = blockIdx.x * 128;

    int tid = threadIdx.x, wid = tid >> 5, lid = tid & 31;
    uint32_t su = smem_u32(sm);
    int* srow_s = (int*)(sm + OFF_SROW);
    float* bias_s = (float*)(sm + OFF_BIAS);

    if (tid < 128) {
        int m = m0 + tid;
        srow_s[tid] = (m < ne) ? d_tok[e][m] : -1;
        bias_s[tid] = b1[(size_t)e * FF + n0 + tid];
    }
    __syncthreads();

    const __half* wbh = d_w1h + ((size_t)e * FF + n0) * DD;

    float c[4][4][4];
#pragma unroll
    for (int i = 0; i < 4; i++)
#pragma unroll
        for (int j = 0; j < 4; j++)
#pragma unroll
            for (int q = 0; q < 4; q++) c[i][j][q] = 0.f;

    // prefetch chunk 0
#pragma unroll
    for (int r = 0; r < 4; r++) {
        int idx = tid + (r << 8);
        int row = idx >> 3, c8 = idx & 7;
        uint32_t so = SWZ((row << 7) + (c8 << 4));
        int tok = srow_s[row];
        unsigned sz = tok >= 0 ? 16u : 0u;
        size_t oa = (size_t)(tok >= 0 ? tok : 0) * DD + (c8 << 3);
        CP16Z(su + T1OFF(0, 0) + so, (const char*)(d_xh + oa), sz);
        CP16Z(su + T1OFF(0, 1) + so, (const char*)(d_xl + oa), sz);
        size_t ob = (size_t)row * DD + (c8 << 3);
        CP16(su + T1OFF(0, 2) + so, (const char*)(wbh + ob));
    }
    CP_COMMIT();

    const int NK = DD / 64;
    int wm0 = (wid >> 2) * 64, wn0 = (wid & 3) * 32;
    for (int i = 0; i < NK; i++) {
        if (i + 1 < NK) {
            int nb = (i + 1) & 1;
            int k0 = (i + 1) * 64;
#pragma unroll
            for (int r = 0; r < 4; r++) {
                int idx = tid + (r << 8);
                int row = idx >> 3, c8 = idx & 7;
                uint32_t so = SWZ((row << 7) + (c8 << 4));
                int tok = srow_s[row];
                unsigned sz = tok >= 0 ? 16u : 0u;
                size_t oa = (size_t)(tok >= 0 ? tok : 0) * DD + k0 + (c8 << 3);
                CP16Z(su + T1OFF(nb, 0) + so, (const char*)(d_xh + oa), sz);
                CP16Z(su + T1OFF(nb, 1) + so, (const char*)(d_xl + oa), sz);
                size_t ob = (size_t)row * DD + k0 + (c8 << 3);
                CP16(su + T1OFF(nb, 2) + so, (const char*)(wbh + ob));
            }
            CP_COMMIT();
            CP_WAIT1();
        } else {
            CP_WAIT0();
        }
        __syncthreads();
        int b = i & 1;
        mma_chunk_g1(c, su + T1OFF(b, 0), su + T1OFF(b, 1), su + T1OFF(b, 2),
                     wm0, wn0, lid);
        __syncthreads();
    }

    // epilogue: bias + exact gelu -> fp16 store (hi only)
    int qr = lid >> 2, qc = (lid & 3) << 1;
#pragma unroll
    for (int i = 0; i < 4; i++) {
#pragma unroll
        for (int h = 0; h < 2; h++) {
            int lrow = wm0 + i * 16 + h * 8 + qr;
            if (m0 + lrow >= ne) continue;
            size_t base = ((size_t)e * TT + m0 + lrow) * FF + n0;
#pragma unroll
            for (int j = 0; j < 4; j++) {
                int colp = wn0 + j * 8 + qc;
                float v0 = c[i][j][h * 2 + 0] + bias_s[colp];
                float v1 = c[i][j][h * 2 + 1] + bias_s[colp + 1];
                float g0 = gelu_exact(v0), g1 = gelu_exact(v1);
                *(__half2*)(d_Hh + base + colp) =
                    __halves2half2(__float2half(g0), __float2half(g1));
            }
        }
    }
}

// ---------------------------------------------------------------------------
// GEMM2: out[tok] += w * ( H[e] @ W2[e] + b2[e] )   (single MMA pass)
// ---------------------------------------------------------------------------
__global__ __launch_bounds__(256, 2) void moe_mma2_kernel(
    const float* __restrict__ b2, float* __restrict__ out) {
    extern __shared__ char sm[];
    int e = blockIdx.z;
    int ne = d_cnt[e];
    int m0 = blockIdx.y * 128;
    if (m0 >= ne) return;
    int n0 = blockIdx.x * 128;

    int tid = threadIdx.x, wid = tid >> 5, lid = tid & 31;
    uint32_t su = smem_u32(sm);
    int* srow_s = (int*)(sm + OFF_SROW);
    float* swt_s = (float*)(sm + OFF_SWT);
    float* bias_s = (float*)(sm + OFF_BIAS);

    if (tid < 128) {
        int m = m0 + tid;
        if (m < ne) { srow_s[tid] = d_tok[e][m]; swt_s[tid] = d_wt[e][m]; }
        else        { srow_s[tid] = 0;           swt_s[tid] = 0.f; }
        bias_s[tid] = b2[(size_t)e * DD + n0 + tid];
    }
    __syncthreads();

    const __half* ah_base = d_Hh + ((size_t)e * TT + m0) * FF;
    const __half* wbh = d_w2h + ((size_t)e * DD + n0) * FF;

    float c[4][4][4];
#pragma unroll
    for (int i = 0; i < 4; i++)
#pragma unroll
        for (int j = 0; j < 4; j++)
#pragma unroll
            for (int q = 0; q < 4; q++) c[i][j][q] = 0.f;

#pragma unroll
    for (int r = 0; r < 4; r++) {
        int idx = tid + (r << 8);
        int row = idx >> 3, c8 = idx & 7;
        uint32_t so = SWZ((row << 7) + (c8 << 4));
        size_t oa = (size_t)row * FF + (c8 << 3);
        CP16(su + T2OFF(0, 0) + so, (const char*)(ah_base + oa));
        CP16(su + T2OFF(0, 1) + so, (const char*)(wbh + oa));
    }
    CP_COMMIT();

    const int NK = FF / 64;
    int wm0 = (wid >> 2) * 64, wn0 = (wid & 3) * 32;
    for (int i = 0; i < NK; i++) {
        if (i + 1 < NK) {
            int nb = (i + 1) & 1;
            int k0 = (i + 1) * 64;
#pragma unroll
            for (int r = 0; r < 4; r++) {
                int idx = tid + (r << 8);
                int row = idx >> 3, c8 = idx & 7;
                uint32_t so = SWZ((row << 7) + (c8 << 4));
                size_t oa = (size_t)row * FF + k0 + (c8 << 3);
                CP16(su + T2OFF(nb, 0) + so, (const char*)(ah_base + oa));
                CP16(su + T2OFF(nb, 1) + so, (const char*)(wbh + oa));
            }
            CP_COMMIT();
            CP_WAIT1();
        } else {
            CP_WAIT0();
        }
        __syncthreads();
        int b = i & 1;
        mma_chunk_g2(c, su + T2OFF(b, 0), su + T2OFF(b, 1), wm0, wn0, lid);
        __syncthreads();
    }

    // epilogue: bias + gate weight, atomic add into out
    int qr = lid >> 2, qc = (lid & 3) << 1;
#pragma unroll
    for (int i = 0; i < 4; i++) {
#pragma unroll
        for (int h = 0; h < 2; h++) {
            int lrow = wm0 + i * 16 + h * 8 + qr;
            if (m0 + lrow >= ne) continue;
            int tok = srow_s[lrow];
            float w = swt_s[lrow];
            float* ob = out + (size_t)tok * DD + n0;
#pragma unroll
            for (int j = 0; j < 4; j++) {
                int colp = wn0 + j * 8 + qc;
                float v0 = c[i][j][h * 2 + 0] + bias_s[colp];
                float v1 = c[i][j][h * 2 + 1] + bias_s[colp + 1];
                atomicAdd(ob + colp, w * v0);
                atomicAdd(ob + colp + 1, w * v1);
            }
        }
    }
}

// ---------------------------------------------------------------------------
extern "C" void kernel_launch(void* const* d_in, const int* in_sizes, int n_in,
                              void* d_out, int out_size) {
    const float* x  = (const float*)d_in[0];
    const float* gw = (const float*)d_in[1];
    const float* gb = (const float*)d_in[2];
    const float* W1 = (const float*)d_in[3];
    const float* b1 = (const float*)d_in[4];
    const float* W2 = (const float*)d_in[5];
    const float* b2 = (const float*)d_in[6];
    float* out = (float*)d_out;

    static int configured = 0;
    if (!configured) {
        cudaFuncSetAttribute((const void*)moe_mma1_kernel,
                             cudaFuncAttributeMaxDynamicSharedMemorySize,
                             SMEM1_BYTES);
        cudaFuncSetAttribute((const void*)moe_mma2_kernel,
                             cudaFuncAttributeMaxDynamicSharedMemorySize,
                             SMEM2_BYTES);
        configured = 1;
    }

    init_kernel<<<(TT * DD / 4) / 256, 256>>>((float4*)out);
    gate_kernel<<<TT / 8, 256>>>(x, gw, gb);
    convert_x_kernel<<<(TT * DD / 4) / 256, 256>>>((const float4*)x);
    transpose_kernel<<<dim3(FF / 32, DD / 32, EE), dim3(32, 8)>>>(W1, 0, DD, FF);
    transpose_kernel<<<dim3(DD / 32, FF / 32, EE), dim3(32, 8)>>>(W2, 1, FF, DD);
    moe_mma1_kernel<<<dim3(FF / 128, TT / 128, EE), 256, SMEM1_BYTES>>>(b1);
    moe_mma2_kernel<<<dim3(DD / 128, TT / 128, EE), 256, SMEM2_BYTES>>>(b2, out);
}

// round 9
// speedup vs baseline: 1.4579x; 1.4579x over previous
#include <cuda_runtime.h>
#include <cuda_fp16.h>
#include <math.h>
#include <stdint.h>

#define TT 4096
#define DD 2048
#define FF 5632
#define EE 8

// ---------------------------------------------------------------------------
// Static scratch (allocation-free per harness rules)
// ---------------------------------------------------------------------------
__device__ int   d_cnt[EE];
__device__ int   d_tok[EE][TT];
__device__ float d_wt[EE][TT];
__device__ __half d_xh[(size_t)TT * DD];
__device__ __half d_xl[(size_t)TT * DD];
__device__ __half d_w1h[(size_t)EE * FF * DD];  // [e][f][d] (B^T)
__device__ __half d_w2h[(size_t)EE * DD * FF];  // [e][d][f] (B^T)
__device__ __half d_Hh[(size_t)EE * TT * FF];   // [e][pos][f]

// ---------------------------------------------------------------------------
// PTX helpers — base-ISA only (no sm_103a-gated features)
// ---------------------------------------------------------------------------
__device__ __forceinline__ uint32_t smem_u32(const void* p) {
    uint32_t a;
    asm("{ .reg .u64 t; cvta.to.shared.u64 t, %1; cvt.u32.u64 %0, t; }"
        : "=r"(a) : "l"(p));
    return a;
}
#define SWZ(o) ((o) ^ (((o) >> 3) & 0x70))

#define CP16(dst, src) \
    asm volatile("cp.async.cg.shared.global [%0], [%1], 16;" \
                 :: "r"(dst), "l"(src))
#define CP16Z(dst, src, sz) \
    asm volatile("cp.async.cg.shared.global [%0], [%1], 16, %2;" \
                 :: "r"(dst), "l"(src), "r"(sz))
#define CP_COMMIT() asm volatile("cp.async.commit_group;" ::: "memory")
#define CP_WAIT0()  asm volatile("cp.async.wait_group 0;" ::: "memory")
#define CP_WAIT1()  asm volatile("cp.async.wait_group 1;" ::: "memory")
#define CP_WAIT2()  asm volatile("cp.async.wait_group 2;" ::: "memory")

__device__ __forceinline__ void ldsm4(uint32_t* r, uint32_t a) {
    asm volatile("ldmatrix.sync.aligned.m8n8.x4.shared.b16 {%0,%1,%2,%3}, [%4];"
                 : "=r"(r[0]), "=r"(r[1]), "=r"(r[2]), "=r"(r[3]) : "r"(a));
}
__device__ __forceinline__ void mma_f16(float* c, const uint32_t* a,
                                        const uint32_t* b) {
    asm volatile(
        "mma.sync.aligned.m16n8k16.row.col.f32.f16.f16.f32 "
        "{%0,%1,%2,%3}, {%4,%5,%6,%7}, {%8,%9}, {%0,%1,%2,%3};"
        : "+f"(c[0]), "+f"(c[1]), "+f"(c[2]), "+f"(c[3])
        : "r"(a[0]), "r"(a[1]), "r"(a[2]), "r"(a[3]), "r"(b[0]), "r"(b[1]));
}
__device__ __forceinline__ float gelu_exact(float h) {
    return 0.5f * h * (1.0f + erff(h * 0.70710678118654752440f));
}

// smem layouts
#define OFF_SROW 0
#define OFF_SWT  512
#define OFF_BIAS 1024
#define OFF_TILE 2048
// GEMM1: 2 stages x 3 tensors (Ah, Al, B)
#define T1OFF(b, t) (OFF_TILE + ((b) * 3 + (t)) * 16384)
#define SMEM1_BYTES (OFF_TILE + 6 * 16384)
// GEMM2: 3 stages x 2 tensors (A, B)
#define T2OFF(b, t) (OFF_TILE + ((b) * 2 + (t)) * 16384)
#define SMEM2_BYTES (OFF_TILE + 6 * 16384)

// ---------------------------------------------------------------------------
__global__ void init_kernel(float4* __restrict__ out) {
    size_t i = (size_t)blockIdx.x * blockDim.x + threadIdx.x;
    out[i] = make_float4(0.f, 0.f, 0.f, 0.f);
    if (blockIdx.x == 0 && threadIdx.x < EE) d_cnt[threadIdx.x] = 0;
}

// ---------------------------------------------------------------------------
__global__ void gate_kernel(const float* __restrict__ x,
                            const float* __restrict__ gw,
                            const float* __restrict__ gb) {
    int t = (int)((blockIdx.x * blockDim.x + threadIdx.x) >> 5);
    int lane = threadIdx.x & 31;
    if (t >= TT) return;
    const float* xr = x + (size_t)t * DD;

    float acc[EE];
#pragma unroll
    for (int e = 0; e < EE; e++) acc[e] = 0.f;
    for (int d = lane; d < DD; d += 32) {
        float xv = __ldg(xr + d);
        const float* g = gw + (size_t)d * EE;
#pragma unroll
        for (int e = 0; e < EE; e++) acc[e] = fmaf(xv, __ldg(g + e), acc[e]);
    }
#pragma unroll
    for (int e = 0; e < EE; e++) {
#pragma unroll
        for (int o = 16; o > 0; o >>= 1)
            acc[e] += __shfl_xor_sync(0xffffffffu, acc[e], o);
    }
    if (lane == 0) {
#pragma unroll
        for (int e = 0; e < EE; e++) acc[e] += gb[e];
        float mx = acc[0];
#pragma unroll
        for (int e = 1; e < EE; e++) mx = fmaxf(mx, acc[e]);
        float p[EE]; float s = 0.f;
#pragma unroll
        for (int e = 0; e < EE; e++) { p[e] = expf(acc[e] - mx); s += p[e]; }
        float inv = 1.f / s;
        int i1 = 0; float v1 = p[0];
#pragma unroll
        for (int e = 1; e < EE; e++) if (p[e] > v1) { v1 = p[e]; i1 = e; }
        int i2 = -1; float v2 = -1.f;
#pragma unroll
        for (int e = 0; e < EE; e++)
            if (e != i1 && p[e] > v2) { v2 = p[e]; i2 = e; }
        int pos = atomicAdd(&d_cnt[i1], 1);
        d_tok[i1][pos] = t; d_wt[i1][pos] = v1 * inv;
        pos = atomicAdd(&d_cnt[i2], 1);
        d_tok[i2][pos] = t; d_wt[i2][pos] = v2 * inv;
    }
}

// ---------------------------------------------------------------------------
// x -> (hi, lo) fp16 split
// ---------------------------------------------------------------------------
__global__ void convert_x_kernel(const float4* __restrict__ x4) {
    size_t i = (size_t)blockIdx.x * blockDim.x + threadIdx.x;
    float4 v = x4[i];
    __half h0 = __float2half(v.x), h1 = __float2half(v.y);
    __half h2 = __float2half(v.z), h3 = __float2half(v.w);
    __half l0 = __float2half(v.x - __half2float(h0));
    __half l1 = __float2half(v.y - __half2float(h1));
    __half l2 = __float2half(v.z - __half2float(h2));
    __half l3 = __float2half(v.w - __half2float(h3));
    *(__half2*)(d_xh + i * 4 + 0) = __halves2half2(h0, h1);
    *(__half2*)(d_xh + i * 4 + 2) = __halves2half2(h2, h3);
    *(__half2*)(d_xl + i * 4 + 0) = __halves2half2(l0, l1);
    *(__half2*)(d_xl + i * 4 + 2) = __halves2half2(l2, l3);
}

// ---------------------------------------------------------------------------
// weight transpose to fp16 with paired half2 stores
// src [e][R][C] -> dst [e][C][R]; block (16,16), tile 32x32
// ---------------------------------------------------------------------------
__global__ void transpose_kernel(const float* __restrict__ src, int which,
                                 int R, int C) {
    __shared__ float t[32][33];
    int e = blockIdx.z;
    const float* S = src + (size_t)e * R * C;
    __half* DH = (which ? d_w2h : d_w1h) + (size_t)e * R * C;
    int c0 = blockIdx.x * 32, r0 = blockIdx.y * 32;
    int tx = threadIdx.x, ty = threadIdx.y;
    int idx = ty * 16 + tx;
#pragma unroll
    for (int jj = 0; jj < 4; jj++) {
        int lin = idx + jj * 256;
        int r = lin >> 5, cc = lin & 31;
        t[r][cc] = S[(size_t)(r0 + r) * C + c0 + cc];
    }
    __syncthreads();
#pragma unroll
    for (int j = 0; j < 2; j++) {
        int c = ty + j * 16;
        __half2 v = __floats2half2_rn(t[2 * tx][c], t[2 * tx + 1][c]);
        *(__half2*)(DH + (size_t)(c0 + c) * R + r0 + 2 * tx) = v;
    }
}

// ---------------------------------------------------------------------------
// GEMM1 chunk: c += (Ah + Al)(128x64) * B(128x64)^T  (B tiles in [n][k])
// ---------------------------------------------------------------------------
__device__ __forceinline__ void mma_chunk_g1(float c[4][4][4], uint32_t sAh,
                                             uint32_t sAl, uint32_t sBh,
                                             int wm0, int wn0, int lid) {
    int mat = lid >> 3, lr = lid & 7;
#pragma unroll
    for (int ks = 0; ks < 4; ks++) {
        uint32_t ah[4][4], al[4][4], bh[4][2];
#pragma unroll
        for (int i = 0; i < 4; i++) {
            int row = wm0 + i * 16 + ((mat & 1) << 3) + lr;
            int col = ks * 16 + ((mat >> 1) << 3);
            uint32_t off = SWZ((row << 7) + (col << 1));
            ldsm4(ah[i], sAh + off);
            ldsm4(al[i], sAl + off);
        }
#pragma unroll
        for (int jp = 0; jp < 2; jp++) {
            int row = wn0 + jp * 16 + ((mat >> 1) << 3) + lr;
            int col = ks * 16 + ((mat & 1) << 3);
            uint32_t off = SWZ((row << 7) + (col << 1));
            uint32_t t4[4];
            ldsm4(t4, sBh + off);
            bh[jp * 2][0] = t4[0]; bh[jp * 2][1] = t4[1];
            bh[jp * 2 + 1][0] = t4[2]; bh[jp * 2 + 1][1] = t4[3];
        }
#pragma unroll
        for (int i = 0; i < 4; i++)
#pragma unroll
            for (int j = 0; j < 4; j++) {
                mma_f16(c[i][j], ah[i], bh[j]);
                mma_f16(c[i][j], al[i], bh[j]);
            }
    }
}

// ---------------------------------------------------------------------------
// GEMM2 chunk: c += A(128x64) * B(128x64)^T  (single pass)
// ---------------------------------------------------------------------------
__device__ __forceinline__ void mma_chunk_g2(float c[4][4][4], uint32_t sA,
                                             uint32_t sBh, int wm0, int wn0,
                                             int lid) {
    int mat = lid >> 3, lr = lid & 7;
#pragma unroll
    for (int ks = 0; ks < 4; ks++) {
        uint32_t ah[4][4], bh[4][2];
#pragma unroll
        for (int i = 0; i < 4; i++) {
            int row = wm0 + i * 16 + ((mat & 1) << 3) + lr;
            int col = ks * 16 + ((mat >> 1) << 3);
            uint32_t off = SWZ((row << 7) + (col << 1));
            ldsm4(ah[i], sA + off);
        }
#pragma unroll
        for (int jp = 0; jp < 2; jp++) {
            int row = wn0 + jp * 16 + ((mat >> 1) << 3) + lr;
            int col = ks * 16 + ((mat & 1) << 3);
            uint32_t off = SWZ((row << 7) + (col << 1));
            uint32_t t4[4];
            ldsm4(t4, sBh + off);
            bh[jp * 2][0] = t4[0]; bh[jp * 2][1] = t4[1];
            bh[jp * 2 + 1][0] = t4[2]; bh[jp * 2 + 1][1] = t4[3];
        }
#pragma unroll
        for (int i = 0; i < 4; i++)
#pragma unroll
            for (int j = 0; j < 4; j++) mma_f16(c[i][j], ah[i], bh[j]);
    }
}

// ---------------------------------------------------------------------------
// GEMM1: H[e,m,:] = gelu( x[tok] @ W1[e] + b1[e] ) -> fp16
// grid: (TT/128 m-tiles fastest, FF/128, EE)
// ---------------------------------------------------------------------------
__global__ __launch_bounds__(256, 2) void moe_mma1_kernel(
    const float* __restrict__ b1) {
    extern __shared__ char sm[];
    int e = blockIdx.z;
    int ne = d_cnt[e];
    int m0 = blockIdx.x * 128;
    if (m0 >= ne) return;
    int n0 = blockIdx.y * 128;

    int tid = threadIdx.x, wid = tid >> 5, lid = tid & 31;
    uint32_t su = smem_u32(sm);
    int* srow_s = (int*)(sm + OFF_SROW);
    float* bias_s = (float*)(sm + OFF_BIAS);

    if (tid < 128) {
        int m = m0 + tid;
        srow_s[tid] = (m < ne) ? d_tok[e][m] : -1;
        bias_s[tid] = b1[(size_t)e * FF + n0 + tid];
    }
    __syncthreads();

    const __half* wbh = d_w1h + ((size_t)e * FF + n0) * DD;

    float c[4][4][4];
#pragma unroll
    for (int i = 0; i < 4; i++)
#pragma unroll
        for (int j = 0; j < 4; j++)
#pragma unroll
            for (int q = 0; q < 4; q++) c[i][j][q] = 0.f;

    // prefetch chunk 0
#pragma unroll
    for (int r = 0; r < 4; r++) {
        int idx = tid + (r << 8);
        int row = idx >> 3, c8 = idx & 7;
        uint32_t so = SWZ((row << 7) + (c8 << 4));
        int tok = srow_s[row];
        unsigned sz = tok >= 0 ? 16u : 0u;
        size_t oa = (size_t)(tok >= 0 ? tok : 0) * DD + (c8 << 3);
        CP16Z(su + T1OFF(0, 0) + so, (const char*)(d_xh + oa), sz);
        CP16Z(su + T1OFF(0, 1) + so, (const char*)(d_xl + oa), sz);
        size_t ob = (size_t)row * DD + (c8 << 3);
        CP16(su + T1OFF(0, 2) + so, (const char*)(wbh + ob));
    }
    CP_COMMIT();

    const int NK = DD / 64;
    int wm0 = (wid >> 2) * 64, wn0 = (wid & 3) * 32;
    for (int i = 0; i < NK; i++) {
        if (i + 1 < NK) {
            int nb = (i + 1) & 1;
            int k0 = (i + 1) * 64;
#pragma unroll
            for (int r = 0; r < 4; r++) {
                int idx = tid + (r << 8);
                int row = idx >> 3, c8 = idx & 7;
                uint32_t so = SWZ((row << 7) + (c8 << 4));
                int tok = srow_s[row];
                unsigned sz = tok >= 0 ? 16u : 0u;
                size_t oa = (size_t)(tok >= 0 ? tok : 0) * DD + k0 + (c8 << 3);
                CP16Z(su + T1OFF(nb, 0) + so, (const char*)(d_xh + oa), sz);
                CP16Z(su + T1OFF(nb, 1) + so, (const char*)(d_xl + oa), sz);
                size_t ob = (size_t)row * DD + k0 + (c8 << 3);
                CP16(su + T1OFF(nb, 2) + so, (const char*)(wbh + ob));
            }
            CP_COMMIT();
            CP_WAIT1();
        } else {
            CP_WAIT0();
        }
        __syncthreads();
        int b = i & 1;
        mma_chunk_g1(c, su + T1OFF(b, 0), su + T1OFF(b, 1), su + T1OFF(b, 2),
                     wm0, wn0, lid);
        __syncthreads();
    }

    // epilogue: bias + exact gelu -> fp16 store (hi only)
    int qr = lid >> 2, qc = (lid & 3) << 1;
#pragma unroll
    for (int i = 0; i < 4; i++) {
#pragma unroll
        for (int h = 0; h < 2; h++) {
            int lrow = wm0 + i * 16 + h * 8 + qr;
            if (m0 + lrow >= ne) continue;
            size_t base = ((size_t)e * TT + m0 + lrow) * FF + n0;
#pragma unroll
            for (int j = 0; j < 4; j++) {
                int colp = wn0 + j * 8 + qc;
                float v0 = c[i][j][h * 2 + 0] + bias_s[colp];
                float v1 = c[i][j][h * 2 + 1] + bias_s[colp + 1];
                float g0 = gelu_exact(v0), g1 = gelu_exact(v1);
                *(__half2*)(d_Hh + base + colp) =
                    __halves2half2(__float2half(g0), __float2half(g1));
            }
        }
    }
}

// ---------------------------------------------------------------------------
// GEMM2 chunk loader (one stage)
// ---------------------------------------------------------------------------
__device__ __forceinline__ void g2_load(uint32_t su, int buf,
                                        const __half* ah_base,
                                        const __half* wbh, int k0, int tid) {
#pragma unroll
    for (int r = 0; r < 4; r++) {
        int idx = tid + (r << 8);
        int row = idx >> 3, c8 = idx & 7;
        uint32_t so = SWZ((row << 7) + (c8 << 4));
        size_t oa = (size_t)row * FF + k0 + (c8 << 3);
        CP16(su + T2OFF(buf, 0) + so, (const char*)(ah_base + oa));
        CP16(su + T2OFF(buf, 1) + so, (const char*)(wbh + oa));
    }
}

// ---------------------------------------------------------------------------
// GEMM2: out[tok] += w * ( H[e] @ W2[e] + b2[e] )
// single MMA pass, 3-stage pipeline; grid: (TT/128, DD/128, EE)
// ---------------------------------------------------------------------------
__global__ __launch_bounds__(256, 2) void moe_mma2_kernel(
    const float* __restrict__ b2, float* __restrict__ out) {
    extern __shared__ char sm[];
    int e = blockIdx.z;
    int ne = d_cnt[e];
    int m0 = blockIdx.x * 128;
    if (m0 >= ne) return;
    int n0 = blockIdx.y * 128;

    int tid = threadIdx.x, wid = tid >> 5, lid = tid & 31;
    uint32_t su = smem_u32(sm);
    int* srow_s = (int*)(sm + OFF_SROW);
    float* swt_s = (float*)(sm + OFF_SWT);
    float* bias_s = (float*)(sm + OFF_BIAS);

    if (tid < 128) {
        int m = m0 + tid;
        if (m < ne) { srow_s[tid] = d_tok[e][m]; swt_s[tid] = d_wt[e][m]; }
        else        { srow_s[tid] = 0;           swt_s[tid] = 0.f; }
        bias_s[tid] = b2[(size_t)e * DD + n0 + tid];
    }
    __syncthreads();

    const __half* ah_base = d_Hh + ((size_t)e * TT + m0) * FF;
    const __half* wbh = d_w2h + ((size_t)e * DD + n0) * FF;

    float c[4][4][4];
#pragma unroll
    for (int i = 0; i < 4; i++)
#pragma unroll
        for (int j = 0; j < 4; j++)
#pragma unroll
            for (int q = 0; q < 4; q++) c[i][j][q] = 0.f;

    // prefetch stages 0, 1
    g2_load(su, 0, ah_base, wbh, 0, tid);
    CP_COMMIT();
    g2_load(su, 1, ah_base, wbh, 64, tid);
    CP_COMMIT();

    const int NK = FF / 64;
    int wm0 = (wid >> 2) * 64, wn0 = (wid & 3) * 32;
    int buf = 0;
    for (int i = 0; i < NK; i++) {
        if (i + 2 < NK) {
            int nb = (i + 2) % 3;
            g2_load(su, nb, ah_base, wbh, (i + 2) * 64, tid);
            CP_COMMIT();
            CP_WAIT2();
        } else if (i + 1 < NK) {
            CP_WAIT1();
        } else {
            CP_WAIT0();
        }
        __syncthreads();
        mma_chunk_g2(c, su + T2OFF(buf, 0), su + T2OFF(buf, 1), wm0, wn0, lid);
        __syncthreads();
        buf = (buf + 1 == 3) ? 0 : buf + 1;
    }

    // epilogue: bias + gate weight, atomic add into out
    int qr = lid >> 2, qc = (lid & 3) << 1;
#pragma unroll
    for (int i = 0; i < 4; i++) {
#pragma unroll
        for (int h = 0; h < 2; h++) {
            int lrow = wm0 + i * 16 + h * 8 + qr;
            if (m0 + lrow >= ne) continue;
            int tok = srow_s[lrow];
            float w = swt_s[lrow];
            float* ob = out + (size_t)tok * DD + n0;
#pragma unroll
            for (int j = 0; j < 4; j++) {
                int colp = wn0 + j * 8 + qc;
                float v0 = c[i][j][h * 2 + 0] + bias_s[colp];
                float v1 = c[i][j][h * 2 + 1] + bias_s[colp + 1];
                atomicAdd(ob + colp, w * v0);
                atomicAdd(ob + colp + 1, w * v1);
            }
        }
    }
}

// ---------------------------------------------------------------------------
extern "C" void kernel_launch(void* const* d_in, const int* in_sizes, int n_in,
                              void* d_out, int out_size) {
    const float* x  = (const float*)d_in[0];
    const float* gw = (const float*)d_in[1];
    const float* gb = (const float*)d_in[2];
    const float* W1 = (const float*)d_in[3];
    const float* b1 = (const float*)d_in[4];
    const float* W2 = (const float*)d_in[5];
    const float* b2 = (const float*)d_in[6];
    float* out = (float*)d_out;

    static int configured = 0;
    if (!configured) {
        cudaFuncSetAttribute((const void*)moe_mma1_kernel,
                             cudaFuncAttributeMaxDynamicSharedMemorySize,
                             SMEM1_BYTES);
        cudaFuncSetAttribute((const void*)moe_mma2_kernel,
                             cudaFuncAttributeMaxDynamicSharedMemorySize,
                             SMEM2_BYTES);
        configured = 1;
    }

    init_kernel<<<(TT * DD / 4) / 256, 256>>>((float4*)out);
    gate_kernel<<<TT / 8, 256>>>(x, gw, gb);
    convert_x_kernel<<<(TT * DD / 4) / 256, 256>>>((const float4*)x);
    transpose_kernel<<<dim3(FF / 32, DD / 32, EE), dim3(16, 16)>>>(W1, 0, DD, FF);
    transpose_kernel<<<dim3(DD / 32, FF / 32, EE), dim3(16, 16)>>>(W2, 1, FF, DD);
    moe_mma1_kernel<<<dim3(TT / 128, FF / 128, EE), 256, SMEM1_BYTES>>>(b1);
    moe_mma2_kernel<<<dim3(TT / 128, DD / 128, EE), 256, SMEM2_BYTES>>>(b2, out);
}

// round 10
// speedup vs baseline: 1.9616x; 1.3455x over previous
#include <cuda_runtime.h>
#include <cuda_fp16.h>
#include <math.h>
#include <stdint.h>

#define TT 4096
#define DD 2048
#define FF 5632
#define EE 8

// ---------------------------------------------------------------------------
// Static scratch (allocation-free per harness rules)
// ---------------------------------------------------------------------------
__device__ int   d_cnt[EE];
__device__ int   d_tok[EE][TT];
__device__ float d_wt[EE][TT];
__device__ __half d_xh[(size_t)TT * DD];
__device__ __half d_w1h[(size_t)EE * FF * DD];  // [e][f][d] (B^T)
__device__ __half d_w2h[(size_t)EE * DD * FF];  // [e][d][f] (B^T)
__device__ __half d_Hh[(size_t)EE * TT * FF];   // [e][pos][f]

// ---------------------------------------------------------------------------
// PTX helpers — base-ISA only (no sm_103a-gated features)
// ---------------------------------------------------------------------------
__device__ __forceinline__ uint32_t smem_u32(const void* p) {
    uint32_t a;
    asm("{ .reg .u64 t; cvta.to.shared.u64 t, %1; cvt.u32.u64 %0, t; }"
        : "=r"(a) : "l"(p));
    return a;
}
#define SWZ(o) ((o) ^ (((o) >> 3) & 0x70))

#define CP16(dst, src) \
    asm volatile("cp.async.cg.shared.global [%0], [%1], 16;" \
                 :: "r"(dst), "l"(src))
#define CP16Z(dst, src, sz) \
    asm volatile("cp.async.cg.shared.global [%0], [%1], 16, %2;" \
                 :: "r"(dst), "l"(src), "r"(sz))
#define CP_COMMIT() asm volatile("cp.async.commit_group;" ::: "memory")
#define CP_WAIT0()  asm volatile("cp.async.wait_group 0;" ::: "memory")
#define CP_WAIT1()  asm volatile("cp.async.wait_group 1;" ::: "memory")
#define CP_WAIT2()  asm volatile("cp.async.wait_group 2;" ::: "memory")

__device__ __forceinline__ void ldsm4(uint32_t* r, uint32_t a) {
    asm volatile("ldmatrix.sync.aligned.m8n8.x4.shared.b16 {%0,%1,%2,%3}, [%4];"
                 : "=r"(r[0]), "=r"(r[1]), "=r"(r[2]), "=r"(r[3]) : "r"(a));
}
__device__ __forceinline__ void mma_f16(float* c, const uint32_t* a,
                                        const uint32_t* b) {
    asm volatile(
        "mma.sync.aligned.m16n8k16.row.col.f32.f16.f16.f32 "
        "{%0,%1,%2,%3}, {%4,%5,%6,%7}, {%8,%9}, {%0,%1,%2,%3};"
        : "+f"(c[0]), "+f"(c[1]), "+f"(c[2]), "+f"(c[3])
        : "r"(a[0]), "r"(a[1]), "r"(a[2]), "r"(a[3]), "r"(b[0]), "r"(b[1]));
}
__device__ __forceinline__ float gelu_exact(float h) {
    return 0.5f * h * (1.0f + erff(h * 0.70710678118654752440f));
}

// smem layouts: header + 3 stages x 2 tensors x 16KB (both GEMMs)
#define OFF_SROW 0
#define OFF_SWT  512
#define OFF_BIAS 1024
#define OFF_TILE 2048
#define TOFF(b, t) (OFF_TILE + ((b) * 2 + (t)) * 16384)
#define SMEM_BYTES (OFF_TILE + 6 * 16384)

// ---------------------------------------------------------------------------
__global__ void init_kernel(float4* __restrict__ out) {
    size_t i = (size_t)blockIdx.x * blockDim.x + threadIdx.x;
    out[i] = make_float4(0.f, 0.f, 0.f, 0.f);
    if (blockIdx.x == 0 && threadIdx.x < EE) d_cnt[threadIdx.x] = 0;
}

// ---------------------------------------------------------------------------
__global__ void gate_kernel(const float* __restrict__ x,
                            const float* __restrict__ gw,
                            const float* __restrict__ gb) {
    int t = (int)((blockIdx.x * blockDim.x + threadIdx.x) >> 5);
    int lane = threadIdx.x & 31;
    if (t >= TT) return;
    const float* xr = x + (size_t)t * DD;

    float acc[EE];
#pragma unroll
    for (int e = 0; e < EE; e++) acc[e] = 0.f;
    for (int d = lane; d < DD; d += 32) {
        float xv = __ldg(xr + d);
        const float* g = gw + (size_t)d * EE;
#pragma unroll
        for (int e = 0; e < EE; e++) acc[e] = fmaf(xv, __ldg(g + e), acc[e]);
    }
#pragma unroll
    for (int e = 0; e < EE; e++) {
#pragma unroll
        for (int o = 16; o > 0; o >>= 1)
            acc[e] += __shfl_xor_sync(0xffffffffu, acc[e], o);
    }
    if (lane == 0) {
#pragma unroll
        for (int e = 0; e < EE; e++) acc[e] += gb[e];
        float mx = acc[0];
#pragma unroll
        for (int e = 1; e < EE; e++) mx = fmaxf(mx, acc[e]);
        float p[EE]; float s = 0.f;
#pragma unroll
        for (int e = 0; e < EE; e++) { p[e] = expf(acc[e] - mx); s += p[e]; }
        float inv = 1.f / s;
        int i1 = 0; float v1 = p[0];
#pragma unroll
        for (int e = 1; e < EE; e++) if (p[e] > v1) { v1 = p[e]; i1 = e; }
        int i2 = -1; float v2 = -1.f;
#pragma unroll
        for (int e = 0; e < EE; e++)
            if (e != i1 && p[e] > v2) { v2 = p[e]; i2 = e; }
        int pos = atomicAdd(&d_cnt[i1], 1);
        d_tok[i1][pos] = t; d_wt[i1][pos] = v1 * inv;
        pos = atomicAdd(&d_cnt[i2], 1);
        d_tok[i2][pos] = t; d_wt[i2][pos] = v2 * inv;
    }
}

// ---------------------------------------------------------------------------
// x -> fp16 (hi only)
// ---------------------------------------------------------------------------
__global__ void convert_x_kernel(const float4* __restrict__ x4) {
    size_t i = (size_t)blockIdx.x * blockDim.x + threadIdx.x;
    float4 v = x4[i];
    __half2 a = __floats2half2_rn(v.x, v.y);
    __half2 b = __floats2half2_rn(v.z, v.w);
    *(__half2*)(d_xh + i * 4 + 0) = a;
    *(__half2*)(d_xh + i * 4 + 2) = b;
}

// ---------------------------------------------------------------------------
// weight transpose to fp16 with paired half2 stores
// src [e][R][C] -> dst [e][C][R]; block (16,16), tile 32x32
// ---------------------------------------------------------------------------
__global__ void transpose_kernel(const float* __restrict__ src, int which,
                                 int R, int C) {
    __shared__ float t[32][33];
    int e = blockIdx.z;
    const float* S = src + (size_t)e * R * C;
    __half* DH = (which ? d_w2h : d_w1h) + (size_t)e * R * C;
    int c0 = blockIdx.x * 32, r0 = blockIdx.y * 32;
    int tx = threadIdx.x, ty = threadIdx.y;
    int idx = ty * 16 + tx;
#pragma unroll
    for (int jj = 0; jj < 4; jj++) {
        int lin = idx + jj * 256;
        int r = lin >> 5, cc = lin & 31;
        t[r][cc] = S[(size_t)(r0 + r) * C + c0 + cc];
    }
    __syncthreads();
#pragma unroll
    for (int j = 0; j < 2; j++) {
        int c = ty + j * 16;
        __half2 v = __floats2half2_rn(t[2 * tx][c], t[2 * tx + 1][c]);
        *(__half2*)(DH + (size_t)(c0 + c) * R + r0 + 2 * tx) = v;
    }
}

// ---------------------------------------------------------------------------
// MMA chunk: c += A(128x64) * B(128x64)^T  (single pass; B tiles in [n][k])
// ---------------------------------------------------------------------------
__device__ __forceinline__ void mma_chunk(float c[4][4][4], uint32_t sA,
                                          uint32_t sBh, int wm0, int wn0,
                                          int lid) {
    int mat = lid >> 3, lr = lid & 7;
#pragma unroll
    for (int ks = 0; ks < 4; ks++) {
        uint32_t ah[4][4], bh[4][2];
#pragma unroll
        for (int i = 0; i < 4; i++) {
            int row = wm0 + i * 16 + ((mat & 1) << 3) + lr;
            int col = ks * 16 + ((mat >> 1) << 3);
            uint32_t off = SWZ((row << 7) + (col << 1));
            ldsm4(ah[i], sA + off);
        }
#pragma unroll
        for (int jp = 0; jp < 2; jp++) {
            int row = wn0 + jp * 16 + ((mat >> 1) << 3) + lr;
            int col = ks * 16 + ((mat & 1) << 3);
            uint32_t off = SWZ((row << 7) + (col << 1));
            uint32_t t4[4];
            ldsm4(t4, sBh + off);
            bh[jp * 2][0] = t4[0]; bh[jp * 2][1] = t4[1];
            bh[jp * 2 + 1][0] = t4[2]; bh[jp * 2 + 1][1] = t4[3];
        }
#pragma unroll
        for (int i = 0; i < 4; i++)
#pragma unroll
            for (int j = 0; j < 4; j++) mma_f16(c[i][j], ah[i], bh[j]);
    }
}

// ---------------------------------------------------------------------------
// loaders (one pipeline stage each)
// ---------------------------------------------------------------------------
__device__ __forceinline__ void g1_load(uint32_t su, int buf,
                                        const int* srow_s,
                                        const __half* wbh, int k0, int tid) {
#pragma unroll
    for (int r = 0; r < 4; r++) {
        int idx = tid + (r << 8);
        int row = idx >> 3, c8 = idx & 7;
        uint32_t so = SWZ((row << 7) + (c8 << 4));
        int tok = srow_s[row];
        unsigned sz = tok >= 0 ? 16u : 0u;
        size_t oa = (size_t)(tok >= 0 ? tok : 0) * DD + k0 + (c8 << 3);
        CP16Z(su + TOFF(buf, 0) + so, (const char*)(d_xh + oa), sz);
        size_t ob = (size_t)row * DD + k0 + (c8 << 3);
        CP16(su + TOFF(buf, 1) + so, (const char*)(wbh + ob));
    }
}

__device__ __forceinline__ void g2_load(uint32_t su, int buf,
                                        const __half* ah_base,
                                        const __half* wbh, int k0, int tid) {
#pragma unroll
    for (int r = 0; r < 4; r++) {
        int idx = tid + (r << 8);
        int row = idx >> 3, c8 = idx & 7;
        uint32_t so = SWZ((row << 7) + (c8 << 4));
        size_t oa = (size_t)row * FF + k0 + (c8 << 3);
        CP16(su + TOFF(buf, 0) + so, (const char*)(ah_base + oa));
        CP16(su + TOFF(buf, 1) + so, (const char*)(wbh + oa));
    }
}

// ---------------------------------------------------------------------------
// GEMM1: H[e,m,:] = gelu( x[tok] @ W1[e] + b1[e] ) -> fp16
// single pass, 3-stage pipeline; grid: (TT/128 fastest, FF/128, EE)
// ---------------------------------------------------------------------------
__global__ __launch_bounds__(256, 2) void moe_mma1_kernel(
    const float* __restrict__ b1) {
    extern __shared__ char sm[];
    int e = blockIdx.z;
    int ne = d_cnt[e];
    int m0 = blockIdx.x * 128;
    if (m0 >= ne) return;
    int n0 = blockIdx.y * 128;

    int tid = threadIdx.x, wid = tid >> 5, lid = tid & 31;
    uint32_t su = smem_u32(sm);
    int* srow_s = (int*)(sm + OFF_SROW);
    float* bias_s = (float*)(sm + OFF_BIAS);

    if (tid < 128) {
        int m = m0 + tid;
        srow_s[tid] = (m < ne) ? d_tok[e][m] : -1;
        bias_s[tid] = b1[(size_t)e * FF + n0 + tid];
    }
    __syncthreads();

    const __half* wbh = d_w1h + ((size_t)e * FF + n0) * DD;

    float c[4][4][4];
#pragma unroll
    for (int i = 0; i < 4; i++)
#pragma unroll
        for (int j = 0; j < 4; j++)
#pragma unroll
            for (int q = 0; q < 4; q++) c[i][j][q] = 0.f;

    g1_load(su, 0, srow_s, wbh, 0, tid);
    CP_COMMIT();
    g1_load(su, 1, srow_s, wbh, 64, tid);
    CP_COMMIT();

    const int NK = DD / 64;
    int wm0 = (wid >> 2) * 64, wn0 = (wid & 3) * 32;
    int buf = 0;
    for (int i = 0; i < NK; i++) {
        if (i + 2 < NK) {
            int nb = (i + 2) % 3;
            g1_load(su, nb, srow_s, wbh, (i + 2) * 64, tid);
            CP_COMMIT();
            CP_WAIT2();
        } else if (i + 1 < NK) {
            CP_WAIT1();
        } else {
            CP_WAIT0();
        }
        __syncthreads();
        mma_chunk(c, su + TOFF(buf, 0), su + TOFF(buf, 1), wm0, wn0, lid);
        __syncthreads();
        buf = (buf + 1 == 3) ? 0 : buf + 1;
    }

    // epilogue: bias + exact gelu -> fp16 store
    int qr = lid >> 2, qc = (lid & 3) << 1;
#pragma unroll
    for (int i = 0; i < 4; i++) {
#pragma unroll
        for (int h = 0; h < 2; h++) {
            int lrow = wm0 + i * 16 + h * 8 + qr;
            if (m0 + lrow >= ne) continue;
            size_t base = ((size_t)e * TT + m0 + lrow) * FF + n0;
#pragma unroll
            for (int j = 0; j < 4; j++) {
                int colp = wn0 + j * 8 + qc;
                float v0 = c[i][j][h * 2 + 0] + bias_s[colp];
                float v1 = c[i][j][h * 2 + 1] + bias_s[colp + 1];
                float g0 = gelu_exact(v0), g1 = gelu_exact(v1);
                *(__half2*)(d_Hh + base + colp) =
                    __halves2half2(__float2half(g0), __float2half(g1));
            }
        }
    }
}

// ---------------------------------------------------------------------------
// GEMM2: out[tok] += w * ( H[e] @ W2[e] + b2[e] )
// single pass, 3-stage pipeline; grid: (TT/128, DD/128, EE)
// ---------------------------------------------------------------------------
__global__ __launch_bounds__(256, 2) void moe_mma2_kernel(
    const float* __restrict__ b2, float* __restrict__ out) {
    extern __shared__ char sm[];
    int e = blockIdx.z;
    int ne = d_cnt[e];
    int m0 = blockIdx.x * 128;
    if (m0 >= ne) return;
    int n0 = blockIdx.y * 128;

    int tid = threadIdx.x, wid = tid >> 5, lid = tid & 31;
    uint32_t su = smem_u32(sm);
    int* srow_s = (int*)(sm + OFF_SROW);
    float* swt_s = (float*)(sm + OFF_SWT);
    float* bias_s = (float*)(sm + OFF_BIAS);

    if (tid < 128) {
        int m = m0 + tid;
        if (m < ne) { srow_s[tid] = d_tok[e][m]; swt_s[tid] = d_wt[e][m]; }
        else        { srow_s[tid] = 0;           swt_s[tid] = 0.f; }
        bias_s[tid] = b2[(size_t)e * DD + n0 + tid];
    }
    __syncthreads();

    const __half* ah_base = d_Hh + ((size_t)e * TT + m0) * FF;
    const __half* wbh = d_w2h + ((size_t)e * DD + n0) * FF;

    float c[4][4][4];
#pragma unroll
    for (int i = 0; i < 4; i++)
#pragma unroll
        for (int j = 0; j < 4; j++)
#pragma unroll
            for (int q = 0; q < 4; q++) c[i][j][q] = 0.f;

    g2_load(su, 0, ah_base, wbh, 0, tid);
    CP_COMMIT();
    g2_load(su, 1, ah_base, wbh, 64, tid);
    CP_COMMIT();

    const int NK = FF / 64;
    int wm0 = (wid >> 2) * 64, wn0 = (wid & 3) * 32;
    int buf = 0;
    for (int i = 0; i < NK; i++) {
        if (i + 2 < NK) {
            int nb = (i + 2) % 3;
            g2_load(su, nb, ah_base, wbh, (i + 2) * 64, tid);
            CP_COMMIT();
            CP_WAIT2();
        } else if (i + 1 < NK) {
            CP_WAIT1();
        } else {
            CP_WAIT0();
        }
        __syncthreads();
        mma_chunk(c, su + TOFF(buf, 0), su + TOFF(buf, 1), wm0, wn0, lid);
        __syncthreads();
        buf = (buf + 1 == 3) ? 0 : buf + 1;
    }

    // epilogue: bias + gate weight, atomic add into out
    int qr = lid >> 2, qc = (lid & 3) << 1;
#pragma unroll
    for (int i = 0; i < 4; i++) {
#pragma unroll
        for (int h = 0; h < 2; h++) {
            int lrow = wm0 + i * 16 + h * 8 + qr;
            if (m0 + lrow >= ne) continue;
            int tok = srow_s[lrow];
            float w = swt_s[lrow];
            float* ob = out + (size_t)tok * DD + n0;
#pragma unroll
            for (int j = 0; j < 4; j++) {
                int colp = wn0 + j * 8 + qc;
                float v0 = c[i][j][h * 2 + 0] + bias_s[colp];
                float v1 = c[i][j][h * 2 + 1] + bias_s[colp + 1];
                atomicAdd(ob + colp, w * v0);
                atomicAdd(ob + colp + 1, w * v1);
            }
        }
    }
}

// ---------------------------------------------------------------------------
extern "C" void kernel_launch(void* const* d_in, const int* in_sizes, int n_in,
                              void* d_out, int out_size) {
    const float* x  = (const float*)d_in[0];
    const float* gw = (const float*)d_in[1];
    const float* gb = (const float*)d_in[2];
    const float* W1 = (const float*)d_in[3];
    const float* b1 = (const float*)d_in[4];
    const float* W2 = (const float*)d_in[5];
    const float* b2 = (const float*)d_in[6];
    float* out = (float*)d_out;

    static int configured = 0;
    if (!configured) {
        cudaFuncSetAttribute((const void*)moe_mma1_kernel,
                             cudaFuncAttributeMaxDynamicSharedMemorySize,
                             SMEM_BYTES);
        cudaFuncSetAttribute((const void*)moe_mma2_kernel,
                             cudaFuncAttributeMaxDynamicSharedMemorySize,
                             SMEM_BYTES);
        configured = 1;
    }

    init_kernel<<<(TT * DD / 4) / 256, 256>>>((float4*)out);
    gate_kernel<<<TT / 8, 256>>>(x, gw, gb);
    convert_x_kernel<<<(TT * DD / 4) / 256, 256>>>((const float4*)x);
    transpose_kernel<<<dim3(FF / 32, DD / 32, EE), dim3(16, 16)>>>(W1, 0, DD, FF);
    transpose_kernel<<<dim3(DD / 32, FF / 32, EE), dim3(16, 16)>>>(W2, 1, FF, DD);
    moe_mma1_kernel<<<dim3(TT / 128, FF / 128, EE), 256, SMEM_BYTES>>>(b1);
    moe_mma2_kernel<<<dim3(TT / 128, DD / 128, EE), 256, SMEM_BYTES>>>(b2, out);
}

// round 11
// speedup vs baseline: 2.0105x; 1.0249x over previous
#include <cuda_runtime.h>
#include <cuda_fp16.h>
#include <math.h>
#include <stdint.h>

#define TT 4096
#define DD 2048
#define FF 5632
#define EE 8

// ---------------------------------------------------------------------------
// Static scratch (allocation-free per harness rules)
// ---------------------------------------------------------------------------
__device__ int   d_cnt[EE];
__device__ int   d_tok[EE][TT];
__device__ float d_wt[EE][TT];
__device__ __half d_xh[(size_t)TT * DD];
__device__ __half d_w1h[(size_t)EE * FF * DD];  // [e][f][d] (B^T)
__device__ __half d_w2h[(size_t)EE * DD * FF];  // [e][d][f] (B^T)
__device__ __half d_Hh[(size_t)EE * TT * FF];   // [e][pos][f]

// ---------------------------------------------------------------------------
// PTX helpers — base-ISA only (no sm_103a-gated features)
// ---------------------------------------------------------------------------
__device__ __forceinline__ uint32_t smem_u32(const void* p) {
    uint32_t a;
    asm("{ .reg .u64 t; cvta.to.shared.u64 t, %1; cvt.u32.u64 %0, t; }"
        : "=r"(a) : "l"(p));
    return a;
}
#define SWZ(o) ((o) ^ (((o) >> 3) & 0x70))

#define CP16(dst, src) \
    asm volatile("cp.async.cg.shared.global [%0], [%1], 16;" \
                 :: "r"(dst), "l"(src))
#define CP16Z(dst, src, sz) \
    asm volatile("cp.async.cg.shared.global [%0], [%1], 16, %2;" \
                 :: "r"(dst), "l"(src), "r"(sz))
#define CP_COMMIT() asm volatile("cp.async.commit_group;" ::: "memory")
#define CP_WAIT0()  asm volatile("cp.async.wait_group 0;" ::: "memory")
#define CP_WAIT1()  asm volatile("cp.async.wait_group 1;" ::: "memory")
#define CP_WAIT2()  asm volatile("cp.async.wait_group 2;" ::: "memory")

__device__ __forceinline__ void ldsm4(uint32_t* r, uint32_t a) {
    asm volatile("ldmatrix.sync.aligned.m8n8.x4.shared.b16 {%0,%1,%2,%3}, [%4];"
                 : "=r"(r[0]), "=r"(r[1]), "=r"(r[2]), "=r"(r[3]) : "r"(a));
}
__device__ __forceinline__ void mma_f16(float* c, const uint32_t* a,
                                        const uint32_t* b) {
    asm volatile(
        "mma.sync.aligned.m16n8k16.row.col.f32.f16.f16.f32 "
        "{%0,%1,%2,%3}, {%4,%5,%6,%7}, {%8,%9}, {%0,%1,%2,%3};"
        : "+f"(c[0]), "+f"(c[1]), "+f"(c[2]), "+f"(c[3])
        : "r"(a[0]), "r"(a[1]), "r"(a[2]), "r"(a[3]), "r"(b[0]), "r"(b[1]));
}
__device__ __forceinline__ float gelu_exact(float h) {
    return 0.5f * h * (1.0f + erff(h * 0.70710678118654752440f));
}

// smem layouts: header + 3 stages x 2 tensors x 16KB (both GEMMs)
#define OFF_SROW 0
#define OFF_SWT  512
#define OFF_BIAS 1024
#define OFF_TILE 2048
#define TOFF(b, t) (OFF_TILE + ((b) * 2 + (t)) * 16384)
#define SMEM_BYTES (OFF_TILE + 6 * 16384)

// ---------------------------------------------------------------------------
__global__ void zero_cnt_kernel() {
    if (threadIdx.x < EE) d_cnt[threadIdx.x] = 0;
}

// ---------------------------------------------------------------------------
__global__ void init_out_kernel(float4* __restrict__ out) {
    size_t i = (size_t)blockIdx.x * blockDim.x + threadIdx.x;
    out[i] = make_float4(0.f, 0.f, 0.f, 0.f);
}

// ---------------------------------------------------------------------------
__global__ void gate_kernel(const float* __restrict__ x,
                            const float* __restrict__ gw,
                            const float* __restrict__ gb) {
    int t = (int)((blockIdx.x * blockDim.x + threadIdx.x) >> 5);
    int lane = threadIdx.x & 31;
    if (t >= TT) return;
    const float* xr = x + (size_t)t * DD;

    float acc[EE];
#pragma unroll
    for (int e = 0; e < EE; e++) acc[e] = 0.f;
    for (int d = lane; d < DD; d += 32) {
        float xv = __ldg(xr + d);
        const float* g = gw + (size_t)d * EE;
#pragma unroll
        for (int e = 0; e < EE; e++) acc[e] = fmaf(xv, __ldg(g + e), acc[e]);
    }
#pragma unroll
    for (int e = 0; e < EE; e++) {
#pragma unroll
        for (int o = 16; o > 0; o >>= 1)
            acc[e] += __shfl_xor_sync(0xffffffffu, acc[e], o);
    }
    if (lane == 0) {
#pragma unroll
        for (int e = 0; e < EE; e++) acc[e] += gb[e];
        float mx = acc[0];
#pragma unroll
        for (int e = 1; e < EE; e++) mx = fmaxf(mx, acc[e]);
        float p[EE]; float s = 0.f;
#pragma unroll
        for (int e = 0; e < EE; e++) { p[e] = expf(acc[e] - mx); s += p[e]; }
        float inv = 1.f / s;
        int i1 = 0; float v1 = p[0];
#pragma unroll
        for (int e = 1; e < EE; e++) if (p[e] > v1) { v1 = p[e]; i1 = e; }
        int i2 = -1; float v2 = -1.f;
#pragma unroll
        for (int e = 0; e < EE; e++)
            if (e != i1 && p[e] > v2) { v2 = p[e]; i2 = e; }
        int pos = atomicAdd(&d_cnt[i1], 1);
        d_tok[i1][pos] = t; d_wt[i1][pos] = v1 * inv;
        pos = atomicAdd(&d_cnt[i2], 1);
        d_tok[i2][pos] = t; d_wt[i2][pos] = v2 * inv;
    }
}

// ---------------------------------------------------------------------------
// x -> fp16 (hi only)
// ---------------------------------------------------------------------------
__global__ void convert_x_kernel(const float4* __restrict__ x4) {
    size_t i = (size_t)blockIdx.x * blockDim.x + threadIdx.x;
    float4 v = x4[i];
    __half2 a = __floats2half2_rn(v.x, v.y);
    __half2 b = __floats2half2_rn(v.z, v.w);
    *(__half2*)(d_xh + i * 4 + 0) = a;
    *(__half2*)(d_xh + i * 4 + 2) = b;
}

// ---------------------------------------------------------------------------
// weight transpose to fp16 with paired half2 stores
// src [e][R][C] -> dst [e][C][R]; block (16,16), tile 32x32
// ---------------------------------------------------------------------------
__global__ void transpose_kernel(const float* __restrict__ src, int which,
                                 int R, int C) {
    __shared__ float t[32][33];
    int e = blockIdx.z;
    const float* S = src + (size_t)e * R * C;
    __half* DH = (which ? d_w2h : d_w1h) + (size_t)e * R * C;
    int c0 = blockIdx.x * 32, r0 = blockIdx.y * 32;
    int tx = threadIdx.x, ty = threadIdx.y;
    int idx = ty * 16 + tx;
#pragma unroll
    for (int jj = 0; jj < 4; jj++) {
        int lin = idx + jj * 256;
        int r = lin >> 5, cc = lin & 31;
        t[r][cc] = S[(size_t)(r0 + r) * C + c0 + cc];
    }
    __syncthreads();
#pragma unroll
    for (int j = 0; j < 2; j++) {
        int c = ty + j * 16;
        __half2 v = __floats2half2_rn(t[2 * tx][c], t[2 * tx + 1][c]);
        *(__half2*)(DH + (size_t)(c0 + c) * R + r0 + 2 * tx) = v;
    }
}

// ---------------------------------------------------------------------------
// MMA chunk: c += A(128x64) * B(128x64)^T  (single pass; B tiles in [n][k])
// ---------------------------------------------------------------------------
__device__ __forceinline__ void mma_chunk(float c[4][4][4], uint32_t sA,
                                          uint32_t sBh, int wm0, int wn0,
                                          int lid) {
    int mat = lid >> 3, lr = lid & 7;
#pragma unroll
    for (int ks = 0; ks < 4; ks++) {
        uint32_t ah[4][4], bh[4][2];
#pragma unroll
        for (int i = 0; i < 4; i++) {
            int row = wm0 + i * 16 + ((mat & 1) << 3) + lr;
            int col = ks * 16 + ((mat >> 1) << 3);
            uint32_t off = SWZ((row << 7) + (col << 1));
            ldsm4(ah[i], sA + off);
        }
#pragma unroll
        for (int jp = 0; jp < 2; jp++) {
            int row = wn0 + jp * 16 + ((mat >> 1) << 3) + lr;
            int col = ks * 16 + ((mat & 1) << 3);
            uint32_t off = SWZ((row << 7) + (col << 1));
            uint32_t t4[4];
            ldsm4(t4, sBh + off);
            bh[jp * 2][0] = t4[0]; bh[jp * 2][1] = t4[1];
            bh[jp * 2 + 1][0] = t4[2]; bh[jp * 2 + 1][1] = t4[3];
        }
#pragma unroll
        for (int i = 0; i < 4; i++)
#pragma unroll
            for (int j = 0; j < 4; j++) mma_f16(c[i][j], ah[i], bh[j]);
    }
}

// ---------------------------------------------------------------------------
// loaders (one pipeline stage each)
// ---------------------------------------------------------------------------
__device__ __forceinline__ void g1_load(uint32_t su, int buf,
                                        const int* srow_s,
                                        const __half* wbh, int k0, int tid) {
#pragma unroll
    for (int r = 0; r < 4; r++) {
        int idx = tid + (r << 8);
        int row = idx >> 3, c8 = idx & 7;
        uint32_t so = SWZ((row << 7) + (c8 << 4));
        int tok = srow_s[row];
        unsigned sz = tok >= 0 ? 16u : 0u;
        size_t oa = (size_t)(tok >= 0 ? tok : 0) * DD + k0 + (c8 << 3);
        CP16Z(su + TOFF(buf, 0) + so, (const char*)(d_xh + oa), sz);
        size_t ob = (size_t)row * DD + k0 + (c8 << 3);
        CP16(su + TOFF(buf, 1) + so, (const char*)(wbh + ob));
    }
}

__device__ __forceinline__ void g2_load(uint32_t su, int buf,
                                        const __half* ah_base,
                                        const __half* wbh, int k0, int tid) {
#pragma unroll
    for (int r = 0; r < 4; r++) {
        int idx = tid + (r << 8);
        int row = idx >> 3, c8 = idx & 7;
        uint32_t so = SWZ((row << 7) + (c8 << 4));
        size_t oa = (size_t)row * FF + k0 + (c8 << 3);
        CP16(su + TOFF(buf, 0) + so, (const char*)(ah_base + oa));
        CP16(su + TOFF(buf, 1) + so, (const char*)(wbh + oa));
    }
}

// ---------------------------------------------------------------------------
// GEMM1: H[e,m,:] = gelu( x[tok] @ W1[e] + b1[e] ) -> fp16
// single pass, 3-stage pipeline; grid: (TT/128 fastest, FF/128, EE)
// ---------------------------------------------------------------------------
__global__ __launch_bounds__(256, 2) void moe_mma1_kernel(
    const float* __restrict__ b1) {
    extern __shared__ char sm[];
    int e = blockIdx.z;
    int ne = d_cnt[e];
    int m0 = blockIdx.x * 128;
    if (m0 >= ne) return;
    int n0 = blockIdx.y * 128;

    int tid = threadIdx.x, wid = tid >> 5, lid = tid & 31;
    uint32_t su = smem_u32(sm);
    int* srow_s = (int*)(sm + OFF_SROW);
    float* bias_s = (float*)(sm + OFF_BIAS);

    if (tid < 128) {
        int m = m0 + tid;
        srow_s[tid] = (m < ne) ? d_tok[e][m] : -1;
        bias_s[tid] = b1[(size_t)e * FF + n0 + tid];
    }
    __syncthreads();

    const __half* wbh = d_w1h + ((size_t)e * FF + n0) * DD;

    float c[4][4][4];
#pragma unroll
    for (int i = 0; i < 4; i++)
#pragma unroll
        for (int j = 0; j < 4; j++)
#pragma unroll
            for (int q = 0; q < 4; q++) c[i][j][q] = 0.f;

    g1_load(su, 0, srow_s, wbh, 0, tid);
    CP_COMMIT();
    g1_load(su, 1, srow_s, wbh, 64, tid);
    CP_COMMIT();

    const int NK = DD / 64;
    int wm0 = (wid >> 2) * 64, wn0 = (wid & 3) * 32;
    int buf = 0;
    for (int i = 0; i < NK; i++) {
        if (i + 2 < NK) {
            int nb = (i + 2) % 3;
            g1_load(su, nb, srow_s, wbh, (i + 2) * 64, tid);
            CP_COMMIT();
            CP_WAIT2();
        } else if (i + 1 < NK) {
            CP_WAIT1();
        } else {
            CP_WAIT0();
        }
        __syncthreads();
        mma_chunk(c, su + TOFF(buf, 0), su + TOFF(buf, 1), wm0, wn0, lid);
        __syncthreads();
        buf = (buf + 1 == 3) ? 0 : buf + 1;
    }

    // epilogue: bias + exact gelu -> fp16 store
    int qr = lid >> 2, qc = (lid & 3) << 1;
#pragma unroll
    for (int i = 0; i < 4; i++) {
#pragma unroll
        for (int h = 0; h < 2; h++) {
            int lrow = wm0 + i * 16 + h * 8 + qr;
            if (m0 + lrow >= ne) continue;
            size_t base = ((size_t)e * TT + m0 + lrow) * FF + n0;
#pragma unroll
            for (int j = 0; j < 4; j++) {
                int colp = wn0 + j * 8 + qc;
                float v0 = c[i][j][h * 2 + 0] + bias_s[colp];
                float v1 = c[i][j][h * 2 + 1] + bias_s[colp + 1];
                float g0 = gelu_exact(v0), g1 = gelu_exact(v1);
                *(__half2*)(d_Hh + base + colp) =
                    __halves2half2(__float2half(g0), __float2half(g1));
            }
        }
    }
}

// ---------------------------------------------------------------------------
// GEMM2: out[tok] += w * ( H[e] @ W2[e] + b2[e] )
// single pass, 3-stage pipeline; grid: (TT/128, DD/128, EE)
// ---------------------------------------------------------------------------
__global__ __launch_bounds__(256, 2) void moe_mma2_kernel(
    const float* __restrict__ b2, float* __restrict__ out) {
    extern __shared__ char sm[];
    int e = blockIdx.z;
    int ne = d_cnt[e];
    int m0 = blockIdx.x * 128;
    if (m0 >= ne) return;
    int n0 = blockIdx.y * 128;

    int tid = threadIdx.x, wid = tid >> 5, lid = tid & 31;
    uint32_t su = smem_u32(sm);
    int* srow_s = (int*)(sm + OFF_SROW);
    float* swt_s = (float*)(sm + OFF_SWT);
    float* bias_s = (float*)(sm + OFF_BIAS);

    if (tid < 128) {
        int m = m0 + tid;
        if (m < ne) { srow_s[tid] = d_tok[e][m]; swt_s[tid] = d_wt[e][m]; }
        else        { srow_s[tid] = 0;           swt_s[tid] = 0.f; }
        bias_s[tid] = b2[(size_t)e * DD + n0 + tid];
    }
    __syncthreads();

    const __half* ah_base = d_Hh + ((size_t)e * TT + m0) * FF;
    const __half* wbh = d_w2h + ((size_t)e * DD + n0) * FF;

    float c[4][4][4];
#pragma unroll
    for (int i = 0; i < 4; i++)
#pragma unroll
        for (int j = 0; j < 4; j++)
#pragma unroll
            for (int q = 0; q < 4; q++) c[i][j][q] = 0.f;

    g2_load(su, 0, ah_base, wbh, 0, tid);
    CP_COMMIT();
    g2_load(su, 1, ah_base, wbh, 64, tid);
    CP_COMMIT();

    const int NK = FF / 64;
    int wm0 = (wid >> 2) * 64, wn0 = (wid & 3) * 32;
    int buf = 0;
    for (int i = 0; i < NK; i++) {
        if (i + 2 < NK) {
            int nb = (i + 2) % 3;
            g2_load(su, nb, ah_base, wbh, (i + 2) * 64, tid);
            CP_COMMIT();
            CP_WAIT2();
        } else if (i + 1 < NK) {
            CP_WAIT1();
        } else {
            CP_WAIT0();
        }
        __syncthreads();
        mma_chunk(c, su + TOFF(buf, 0), su + TOFF(buf, 1), wm0, wn0, lid);
        __syncthreads();
        buf = (buf + 1 == 3) ? 0 : buf + 1;
    }

    // epilogue: bias + gate weight, atomic add into out
    int qr = lid >> 2, qc = (lid & 3) << 1;
#pragma unroll
    for (int i = 0; i < 4; i++) {
#pragma unroll
        for (int h = 0; h < 2; h++) {
            int lrow = wm0 + i * 16 + h * 8 + qr;
            if (m0 + lrow >= ne) continue;
            int tok = srow_s[lrow];
            float w = swt_s[lrow];
            float* ob = out + (size_t)tok * DD + n0;
#pragma unroll
            for (int j = 0; j < 4; j++) {
                int colp = wn0 + j * 8 + qc;
                float v0 = c[i][j][h * 2 + 0] + bias_s[colp];
                float v1 = c[i][j][h * 2 + 1] + bias_s[colp + 1];
                atomicAdd(ob + colp, w * v0);
                atomicAdd(ob + colp + 1, w * v1);
            }
        }
    }
}

// ---------------------------------------------------------------------------
extern "C" void kernel_launch(void* const* d_in, const int* in_sizes, int n_in,
                              void* d_out, int out_size) {
    const float* x  = (const float*)d_in[0];
    const float* gw = (const float*)d_in[1];
    const float* gb = (const float*)d_in[2];
    const float* W1 = (const float*)d_in[3];
    const float* b1 = (const float*)d_in[4];
    const float* W2 = (const float*)d_in[5];
    const float* b2 = (const float*)d_in[6];
    float* out = (float*)d_out;

    static int configured = 0;
    static cudaStream_t s1, s2;
    static cudaEvent_t eFork1, eFork2, e1, e2;
    if (!configured) {
        cudaFuncSetAttribute((const void*)moe_mma1_kernel,
                             cudaFuncAttributeMaxDynamicSharedMemorySize,
                             SMEM_BYTES);
        cudaFuncSetAttribute((const void*)moe_mma2_kernel,
                             cudaFuncAttributeMaxDynamicSharedMemorySize,
                             SMEM_BYTES);
        cudaStreamCreateWithFlags(&s1, cudaStreamNonBlocking);
        cudaStreamCreateWithFlags(&s2, cudaStreamNonBlocking);
        cudaEventCreateWithFlags(&eFork1, cudaEventDisableTiming);
        cudaEventCreateWithFlags(&eFork2, cudaEventDisableTiming);
        cudaEventCreateWithFlags(&e1, cudaEventDisableTiming);
        cudaEventCreateWithFlags(&e2, cudaEventDisableTiming);
        configured = 1;
    }

    // fork side streams off the main (capture-origin) stream
    cudaEventRecord(eFork1, 0);
    cudaEventRecord(eFork2, 0);
    cudaStreamWaitEvent(s1, eFork1, 0);
    cudaStreamWaitEvent(s2, eFork2, 0);

    // s1: x convert + W1 transpose (GEMM1 prerequisites)
    convert_x_kernel<<<(TT * DD / 4) / 256, 256, 0, s1>>>((const float4*)x);
    transpose_kernel<<<dim3(FF / 32, DD / 32, EE), dim3(16, 16), 0, s1>>>(
        W1, 0, DD, FF);
    cudaEventRecord(e1, s1);

    // s2: W2 transpose + out zeroing (GEMM2 prerequisites)
    transpose_kernel<<<dim3(DD / 32, FF / 32, EE), dim3(16, 16), 0, s2>>>(
        W2, 1, FF, DD);
    init_out_kernel<<<(TT * DD / 4) / 256, 256, 0, s2>>>((float4*)out);
    cudaEventRecord(e2, s2);

    // s0: gating chain, then GEMMs
    zero_cnt_kernel<<<1, 32>>>();
    gate_kernel<<<TT / 8, 256>>>(x, gw, gb);

    cudaStreamWaitEvent(0, e1, 0);
    moe_mma1_kernel<<<dim3(TT / 128, FF / 128, EE), 256, SMEM_BYTES>>>(b1);

    cudaStreamWaitEvent(0, e2, 0);
    moe_mma2_kernel<<<dim3(TT / 128, DD / 128, EE), 256, SMEM_BYTES>>>(b2, out);
}